// round 3
// baseline (speedup 1.0000x reference)
#include <cuda_runtime.h>
#include <cuda_bf16.h>
#include <cstdint>

// ---------------- problem constants ----------------
#define BN 32
#define TN 2048
#define HN 1024
#define UN 1024

// ---------------- device scratch (no cudaMalloc allowed) ----------------
__device__ float g_qbias[BN * UN];   // q@Wq^T + W_b
__device__ float g_score[BN * TN];   // pre-softmax scores (V_b dropped: softmax-invariant)

// ---------------- helpers ----------------
__device__ __forceinline__ uint32_t smem_u32(const void* p) {
    uint32_t a;
    asm("{ .reg .u64 t; cvta.to.shared.u64 t, %1; cvt.u32.u64 %0, t; }" : "=r"(a) : "l"(p));
    return a;
}
__device__ __forceinline__ uint32_t cvt_tf32(float f) {
    uint32_t u; asm("cvt.rna.tf32.f32 %0, %1;" : "=r"(u) : "f"(f)); return u;
}
__device__ __forceinline__ void mma8(float* d, const uint32_t* a, uint32_t b0, uint32_t b1) {
    asm volatile(
        "mma.sync.aligned.m16n8k8.row.col.f32.tf32.tf32.f32 "
        "{%0,%1,%2,%3}, {%4,%5,%6,%7}, {%8,%9}, {%0,%1,%2,%3};"
        : "+f"(d[0]), "+f"(d[1]), "+f"(d[2]), "+f"(d[3])
        : "r"(a[0]), "r"(a[1]), "r"(a[2]), "r"(a[3]), "r"(b0), "r"(b1));
}
#define CP16(dst, src) \
    asm volatile("cp.async.cg.shared.global [%0], [%1], 16;" :: "r"(dst), "l"(src))

// ---------------- smem layout for gemm kernel (float offsets) ----------------
// A slabs: [128][36] x2, B slabs: [256][36] x2 (stride 36 = conflict-free frags)
#define OFF_A0 0
#define OFF_A1 (128 * 36)
#define OFF_B0 (2 * 128 * 36)
#define OFF_B1 (2 * 128 * 36 + 256 * 36)
#define OFF_QB (2 * 128 * 36 + 2 * 256 * 36)
#define OFF_VW (OFF_QB + 256)
#define OFF_SC (OFF_VW + 256)
#define SMEM_FLOATS (OFF_SC + 512)
#define SMEM_BYTES (SMEM_FLOATS * 4)

// =================== kernel 0: qbias[b][u] = q[b] . Wq[u] + W_b[u] ===================
// 128 blocks x 256 threads; warp owns one u row, loops over batches (Wq read once).
__global__ void __launch_bounds__(256) qbias_kernel(const float* __restrict__ q,
                                                    const float* __restrict__ W,
                                                    const float* __restrict__ Wb) {
    int tid = threadIdx.x, lane = tid & 31, w = tid >> 5;
    int u = blockIdx.x * 8 + w;
    const float* wrow = W + (size_t)u * (2 * HN) + HN;   // Wq = W_w[:, H:]
    float wreg[32];
#pragma unroll
    for (int i = 0; i < 32; i++) wreg[i] = wrow[lane + i * 32];
    float wb = Wb[u];
    for (int b = 0; b < BN; b++) {
        const float* qb = q + b * HN;
        float acc = 0.f;
#pragma unroll
        for (int i = 0; i < 32; i++) acc = fmaf(wreg[i], qb[lane + i * 32], acc);
#pragma unroll
        for (int o = 16; o; o >>= 1) acc += __shfl_xor_sync(0xFFFFFFFFu, acc, o);
        if (lane == 0) g_qbias[b * UN + u] = acc + wb;
    }
}

// =================== kernel 1: fused tf32 GEMM + tanh reduce ===================
// CTA: M=128 rows x N=256 (4 sequential N-quarters = full U). 512 thr, 4x4 warps,
// warp tile 32x64, mma.m16n8k8.tf32, cp.async double-buffered K-slabs of 32.
__global__ void __launch_bounds__(512, 1)
gemm_score_kernel(const float* __restrict__ values,
                  const float* __restrict__ Ww,
                  const float* __restrict__ Vw) {
    extern __shared__ float sm[];
    const uint32_t sbase = smem_u32(sm);
    const int tid = threadIdx.x;
    const int lane = tid & 31, wid = tid >> 5;
    const int wm = wid & 3, wn = wid >> 2;             // 4 (M) x 4 (N) warp grid
    const size_t m0 = (size_t)blockIdx.x * 128;
    const int b = blockIdx.x >> 4;                     // 16 M-tiles per batch

    sm[OFF_SC + tid] = 0.f;                            // zero score partials

    // ---- cooperative slab loader: A 128x32 f32, B 256x32 f32 ----
    auto load_slab = [&](int ks, int buf, int u0) {
        int k0 = ks * 32;
        uint32_t ab = sbase + (buf ? OFF_A1 : OFF_A0) * 4;
        uint32_t bb = sbase + (buf ? OFF_B1 : OFF_B0) * 4;
#pragma unroll
        for (int i = 0; i < 2; i++) {
            int idx = tid + i * 512;
            int row = idx >> 3, c = idx & 7;
            const float* g = values + (m0 + row) * HN + k0 + c * 4;
            CP16(ab + (uint32_t)(row * 36 + c * 4) * 4, g);
        }
#pragma unroll
        for (int i = 0; i < 4; i++) {
            int idx = tid + i * 512;
            int row = idx >> 3, c = idx & 7;
            const float* g = Ww + (size_t)(0 + u0 + row) * (2 * HN) + k0 + c * 4; // Wv = W_w[:, :H]
            CP16(bb + (uint32_t)(row * 36 + c * 4) * 4, g);
        }
        asm volatile("cp.async.commit_group;" ::: "memory");
    };

    float acc[2][8][4];

    for (int nt = 0; nt < 4; nt++) {
        const int u0 = nt * 256;
        if (tid < 256) {
            sm[OFF_QB + tid] = g_qbias[b * UN + u0 + tid];
            sm[OFF_VW + tid] = Vw[u0 + tid];
        }
#pragma unroll
        for (int i = 0; i < 2; i++)
#pragma unroll
            for (int j = 0; j < 8; j++)
#pragma unroll
                for (int k = 0; k < 4; k++) acc[i][j][k] = 0.f;

        load_slab(0, 0, u0);
        load_slab(1, 1, u0);

        for (int ks = 0; ks < 32; ks++) {
            asm volatile("cp.async.wait_group 1;" ::: "memory");
            __syncthreads();
            const float* As = sm + ((ks & 1) ? OFF_A1 : OFF_A0);
            const float* Bs = sm + ((ks & 1) ? OFF_B1 : OFF_B0);
#pragma unroll
            for (int ksub = 0; ksub < 4; ksub++) {
                const int kk = ksub * 8;
                uint32_t a[2][4];
#pragma unroll
                for (int ms = 0; ms < 2; ms++) {
                    int r = wm * 32 + ms * 16 + (lane >> 2);
                    int c = kk + (lane & 3);
                    a[ms][0] = cvt_tf32(As[r * 36 + c]);
                    a[ms][1] = cvt_tf32(As[(r + 8) * 36 + c]);
                    a[ms][2] = cvt_tf32(As[r * 36 + c + 4]);
                    a[ms][3] = cvt_tf32(As[(r + 8) * 36 + c + 4]);
                }
#pragma unroll
                for (int ns = 0; ns < 8; ns++) {
                    int n = wn * 64 + ns * 8 + (lane >> 2);
                    uint32_t b0 = cvt_tf32(Bs[n * 36 + kk + (lane & 3)]);
                    uint32_t b1 = cvt_tf32(Bs[n * 36 + kk + (lane & 3) + 4]);
                    mma8(acc[0][ns], a[0], b0, b1);
                    mma8(acc[1][ns], a[1], b0, b1);
                }
            }
            __syncthreads();
            if (ks + 2 < 32) load_slab(ks + 2, ks & 1, u0);
            else asm volatile("cp.async.commit_group;" ::: "memory");
        }
        asm volatile("cp.async.wait_group 0;" ::: "memory");

        // ---- epilogue: rsum[row] += tanh(pre + qbias) * Vw over this N-quarter ----
        float rsum[2][2] = {{0.f, 0.f}, {0.f, 0.f}};    // [ms][hi(+8)]
#pragma unroll
        for (int ms = 0; ms < 2; ms++)
#pragma unroll
            for (int ns = 0; ns < 8; ns++)
#pragma unroll
                for (int d = 0; d < 4; d++) {
                    int col = wn * 64 + ns * 8 + (lane & 3) * 2 + (d & 1);
                    float x = acc[ms][ns][d] + sm[OFF_QB + col];
                    float e = __expf(x + x);
                    float th = 1.f - 2.f / (e + 1.f);    // exact tanh, stable both tails
                    rsum[ms][d >> 1] = fmaf(th, sm[OFF_VW + col], rsum[ms][d >> 1]);
                }
#pragma unroll
        for (int ms = 0; ms < 2; ms++)
#pragma unroll
            for (int hi = 0; hi < 2; hi++) {
                float v = rsum[ms][hi];
                v += __shfl_xor_sync(0xFFFFFFFFu, v, 1);
                v += __shfl_xor_sync(0xFFFFFFFFu, v, 2);
                if ((lane & 3) == 0) {
                    int row = wm * 32 + ms * 16 + hi * 8 + (lane >> 2);
                    sm[OFF_SC + row * 4 + wn] += v;      // unique (row, wn) writer
                }
            }
        __syncthreads();
    }

    if (tid < 128)
        g_score[m0 + tid] = sm[OFF_SC + tid * 4] + sm[OFF_SC + tid * 4 + 1] +
                            sm[OFF_SC + tid * 4 + 2] + sm[OFF_SC + tid * 4 + 3];
}

// =================== kernel 2: softmax over T per batch ===================
__global__ void __launch_bounds__(256) softmax_kernel(float* __restrict__ out) {
    __shared__ float red[256];
    int b = blockIdx.x, tid = threadIdx.x;
    float loc[8];
    float mx = -1e30f;
#pragma unroll
    for (int i = 0; i < 8; i++) {
        loc[i] = g_score[b * TN + tid + i * 256];
        mx = fmaxf(mx, loc[i]);
    }
    red[tid] = mx; __syncthreads();
    for (int s = 128; s; s >>= 1) { if (tid < s) red[tid] = fmaxf(red[tid], red[tid + s]); __syncthreads(); }
    float m = red[0]; __syncthreads();
    float sum = 0.f;
#pragma unroll
    for (int i = 0; i < 8; i++) { loc[i] = __expf(loc[i] - m); sum += loc[i]; }
    red[tid] = sum; __syncthreads();
    for (int s = 128; s; s >>= 1) { if (tid < s) red[tid] += red[tid + s]; __syncthreads(); }
    float inv = 1.f / red[0];
#pragma unroll
    for (int i = 0; i < 8; i++)
        out[BN * HN + b * TN + tid + i * 256] = loc[i] * inv;
}

// =================== kernel 3: context[b][col] = sum_t w[b][t] * values[b][t][col] ===================
// grid (16, 32): 64-col chunk x batch; 256 thr = 64 cols x 4 t-slices.
__global__ void __launch_bounds__(256) context_kernel(const float* __restrict__ values,
                                                      float* __restrict__ out) {
    __shared__ float ws[TN];
    __shared__ float part[4][64];
    int b = blockIdx.y;
    int tid = threadIdx.x, tc = tid & 63, tq = tid >> 6;
    int col = blockIdx.x * 64 + tc;
    for (int i = tid; i < TN; i += 256) ws[i] = out[BN * HN + b * TN + i];
    __syncthreads();
    const float* vp = values + ((size_t)b * TN + tq * 512) * HN + col;
    float acc = 0.f;
#pragma unroll 8
    for (int t = 0; t < 512; t++)
        acc = fmaf(ws[tq * 512 + t], vp[(size_t)t * HN], acc);
    part[tq][tc] = acc;
    __syncthreads();
    if (tq == 0)
        out[b * HN + col] = part[0][tc] + part[1][tc] + part[2][tc] + part[3][tc];
}

// =================== launch ===================
extern "C" void kernel_launch(void* const* d_in, const int* in_sizes, int n_in,
                              void* d_out, int out_size) {
    const float* q      = (const float*)d_in[0];   // (1,32,1024)
    const float* values = (const float*)d_in[1];   // (32,2048,1024)
    const float* Ww     = (const float*)d_in[2];   // (1024,2048)
    const float* Wb     = (const float*)d_in[3];   // (1024,)
    const float* Vw     = (const float*)d_in[4];   // (1,1024)
    // d_in[5] = V_b : softmax-invariant, unused
    float* out = (float*)d_out;                    // [context 32*1024 | weights 32*2048]

    qbias_kernel<<<128, 256>>>(q, Ww, Wb);

    cudaFuncSetAttribute(gemm_score_kernel,
                         cudaFuncAttributeMaxDynamicSharedMemorySize, SMEM_BYTES);
    gemm_score_kernel<<<512, 512, SMEM_BYTES>>>(values, Ww, Vw);

    softmax_kernel<<<32, 256>>>(out);

    context_kernel<<<dim3(16, 32), 256>>>(values, out);
}

// round 4
// speedup vs baseline: 1.1306x; 1.1306x over previous
#include <cuda_runtime.h>
#include <cuda_bf16.h>
#include <cstdint>

// ---------------- problem constants ----------------
#define BN 32
#define TN 2048
#define HN 1024
#define UN 1024

// ---------------- device scratch (no cudaMalloc allowed) ----------------
__device__ float g_qbias[BN * UN];   // q@Wq^T + W_b
__device__ float g_score[BN * TN];   // pre-softmax scores (V_b dropped: softmax-invariant)

// ---------------- helpers ----------------
__device__ __forceinline__ uint32_t smem_u32(const void* p) {
    uint32_t a;
    asm("{ .reg .u64 t; cvta.to.shared.u64 t, %1; cvt.u32.u64 %0, t; }" : "=r"(a) : "l"(p));
    return a;
}
__device__ __forceinline__ void mma8(float* d, const uint32_t* a, uint32_t b0, uint32_t b1) {
    asm volatile(
        "mma.sync.aligned.m16n8k8.row.col.f32.tf32.tf32.f32 "
        "{%0,%1,%2,%3}, {%4,%5,%6,%7}, {%8,%9}, {%0,%1,%2,%3};"
        : "+f"(d[0]), "+f"(d[1]), "+f"(d[2]), "+f"(d[3])
        : "r"(a[0]), "r"(a[1]), "r"(a[2]), "r"(a[3]), "r"(b0), "r"(b1));
}
// ldmatrix x4 on b16: one 8x8 b16 tile == 8x4 tf32 tile; mapping matches tf32 mma frags.
__device__ __forceinline__ void ldsm4(uint32_t* r, uint32_t addr) {
    asm volatile("ldmatrix.sync.aligned.m8n8.x4.shared.b16 {%0,%1,%2,%3}, [%4];"
        : "=r"(r[0]), "=r"(r[1]), "=r"(r[2]), "=r"(r[3]) : "r"(addr));
}
#define CP16(dst, src) \
    asm volatile("cp.async.cg.shared.global [%0], [%1], 16;" :: "r"(dst), "l"(src))

// ---------------- gemm smem layout (float offsets) ----------------
// per stage: A [128][36] + B [256][36]; 3 stages
#define STG_A 4608
#define STG   13824
#define OFF_QB (3 * STG)
#define OFF_VW (OFF_QB + 256)
#define OFF_SC (OFF_VW + 256)
#define SMEM_FLOATS (OFF_SC + 512)
#define SMEM_BYTES (SMEM_FLOATS * 4)

// =================== kernel 0: qbias[b][u] = q[b] . Wq[u] + W_b[u] ===================
__global__ void __launch_bounds__(256) qbias_kernel(const float* __restrict__ q,
                                                    const float* __restrict__ W,
                                                    const float* __restrict__ Wb) {
    int tid = threadIdx.x, lane = tid & 31, w = tid >> 5;
    int u = blockIdx.x * 8 + w;
    const float* wrow = W + (size_t)u * (2 * HN) + HN;   // Wq = W_w[:, H:]
    float wreg[32];
#pragma unroll
    for (int i = 0; i < 32; i++) wreg[i] = wrow[lane + i * 32];
    float wb = Wb[u];
    for (int b = 0; b < BN; b++) {
        const float* qb = q + b * HN;
        float acc = 0.f;
#pragma unroll
        for (int i = 0; i < 32; i++) acc = fmaf(wreg[i], qb[lane + i * 32], acc);
#pragma unroll
        for (int o = 16; o; o >>= 1) acc += __shfl_xor_sync(0xFFFFFFFFu, acc, o);
        if (lane == 0) g_qbias[b * UN + u] = acc + wb;
    }
}

// =================== kernel 1: fused tf32 GEMM + tanh reduce ===================
// 256 thr, 8 warps: wm = wid&1 (2 in M), wn = wid>>1 (4 in N). Warp tile 64x64.
// CTA tile M=128 x N=256, 4 sequential N-quarters. K-slab 32, 3-stage cp.async.
// Raw fp32 bits fed to tf32 mma (RZ); first-order truncation bias cancelled by
// scaling acc with 1.000677 in the epilogue.
__global__ void __launch_bounds__(256, 1)
gemm_score_kernel(const float* __restrict__ values,
                  const float* __restrict__ Ww,
                  const float* __restrict__ Vw) {
    extern __shared__ float sm[];
    const uint32_t sbase = smem_u32(sm);
    const int tid = threadIdx.x;
    const int lane = tid & 31, wid = tid >> 5;
    const int wm = wid & 1, wn = wid >> 1;
    const size_t m0 = (size_t)blockIdx.x * 128;
    const int b = blockIdx.x >> 4;                 // 16 M-tiles per batch

    sm[OFF_SC + tid] = 0.f;
    sm[OFF_SC + 256 + tid] = 0.f;

    // per-lane ldmatrix byte offsets (within a stage)
    const uint32_t a_lane =
        (uint32_t)(((wm * 64 + ((lane >> 3) & 1) * 8 + (lane & 7)) * 36 +
                    ((lane >> 4) & 1) * 4) * 4);
    const uint32_t b_lane =
        (uint32_t)((STG_A + (wn * 64 + ((lane >> 4) & 1) * 8 + (lane & 7)) * 36 +
                    ((lane >> 3) & 1) * 4) * 4);

    auto load_slab = [&](int ks, int stg, int u0) {
        const int k0 = ks * 32;
        const uint32_t ab = sbase + (uint32_t)(stg * STG) * 4;
        const uint32_t bb = ab + STG_A * 4;
#pragma unroll
        for (int i = 0; i < 4; i++) {
            int idx = tid + i * 256;
            int row = idx >> 3, c = idx & 7;
            CP16(ab + (uint32_t)(row * 36 + c * 4) * 4,
                 values + (m0 + row) * HN + k0 + c * 4);
        }
#pragma unroll
        for (int i = 0; i < 8; i++) {
            int idx = tid + i * 256;
            int row = idx >> 3, c = idx & 7;
            CP16(bb + (uint32_t)(row * 36 + c * 4) * 4,
                 Ww + (size_t)(u0 + row) * (2 * HN) + k0 + c * 4);   // Wv = W_w[:, :H]
        }
        asm volatile("cp.async.commit_group;" ::: "memory");
    };

    float acc[4][8][4];

    for (int nt = 0; nt < 4; nt++) {
        const int u0 = nt * 256;
        sm[OFF_QB + tid] = g_qbias[b * UN + u0 + tid];
        sm[OFF_VW + tid] = Vw[u0 + tid];
#pragma unroll
        for (int i = 0; i < 4; i++)
#pragma unroll
            for (int j = 0; j < 8; j++)
#pragma unroll
                for (int k = 0; k < 4; k++) acc[i][j][k] = 0.f;

        load_slab(0, 0, u0);
        load_slab(1, 1, u0);

        for (int ks = 0; ks < 32; ks++) {
            asm volatile("cp.async.wait_group 1;" ::: "memory");
            __syncthreads();
            if (ks + 2 < 32) load_slab(ks + 2, (ks + 2) % 3, u0);
            else asm volatile("cp.async.commit_group;" ::: "memory");

            const uint32_t stg_base = sbase + (uint32_t)((ks % 3) * STG) * 4;
            const uint32_t abase = stg_base + a_lane;
            const uint32_t bbase = stg_base + b_lane;
#pragma unroll
            for (int kk8 = 0; kk8 < 4; kk8++) {
                const uint32_t kb = kk8 * 32;          // 8 floats = 32B
                uint32_t af[4][4], bf[4][4];
#pragma unroll
                for (int ms = 0; ms < 4; ms++)
                    ldsm4(af[ms], abase + ms * (16 * 36 * 4) + kb);
#pragma unroll
                for (int j = 0; j < 4; j++)
                    ldsm4(bf[j], bbase + j * (16 * 36 * 4) + kb);
#pragma unroll
                for (int ms = 0; ms < 4; ms++)
#pragma unroll
                    for (int j = 0; j < 4; j++) {
                        mma8(acc[ms][2 * j],     af[ms], bf[j][0], bf[j][1]);
                        mma8(acc[ms][2 * j + 1], af[ms], bf[j][2], bf[j][3]);
                    }
            }
        }

        // ---- epilogue: rsum[row] += tanh(comp*acc + qbias) * Vw ----
        const float comp = 1.000677f;   // cancels tf32 RZ truncation bias (2*2^-11*ln2)
        float rsum[4][2];
#pragma unroll
        for (int ms = 0; ms < 4; ms++) { rsum[ms][0] = 0.f; rsum[ms][1] = 0.f; }
#pragma unroll
        for (int ms = 0; ms < 4; ms++)
#pragma unroll
            for (int ns = 0; ns < 8; ns++)
#pragma unroll
                for (int d = 0; d < 4; d++) {
                    int col = wn * 64 + ns * 8 + (lane & 3) * 2 + (d & 1);
                    float x = fmaf(acc[ms][ns][d], comp, sm[OFF_QB + col]);
                    float e = __expf(x + x);
                    float th = 1.f - 2.f / (e + 1.f);   // exact tanh, stable both tails
                    rsum[ms][d >> 1] = fmaf(th, sm[OFF_VW + col], rsum[ms][d >> 1]);
                }
#pragma unroll
        for (int ms = 0; ms < 4; ms++)
#pragma unroll
            for (int hi = 0; hi < 2; hi++) {
                float v = rsum[ms][hi];
                v += __shfl_xor_sync(0xFFFFFFFFu, v, 1);
                v += __shfl_xor_sync(0xFFFFFFFFu, v, 2);
                if ((lane & 3) == 0) {
                    int row = wm * 64 + ms * 16 + hi * 8 + (lane >> 2);
                    sm[OFF_SC + row * 4 + wn] += v;     // unique (row, wn) writer
                }
            }
        __syncthreads();   // epilogue reads done before qb/vw restage + smem reuse
    }

    if (tid < 128)
        g_score[m0 + tid] = sm[OFF_SC + tid * 4] + sm[OFF_SC + tid * 4 + 1] +
                            sm[OFF_SC + tid * 4 + 2] + sm[OFF_SC + tid * 4 + 3];
}

// =================== kernel 2: softmax over T per batch ===================
__global__ void __launch_bounds__(256) softmax_kernel(float* __restrict__ out) {
    __shared__ float red[256];
    int b = blockIdx.x, tid = threadIdx.x;
    float loc[8];
    float mx = -1e30f;
#pragma unroll
    for (int i = 0; i < 8; i++) {
        loc[i] = g_score[b * TN + tid + i * 256];
        mx = fmaxf(mx, loc[i]);
    }
    red[tid] = mx; __syncthreads();
    for (int s = 128; s; s >>= 1) { if (tid < s) red[tid] = fmaxf(red[tid], red[tid + s]); __syncthreads(); }
    float m = red[0]; __syncthreads();
    float sum = 0.f;
#pragma unroll
    for (int i = 0; i < 8; i++) { loc[i] = __expf(loc[i] - m); sum += loc[i]; }
    red[tid] = sum; __syncthreads();
    for (int s = 128; s; s >>= 1) { if (tid < s) red[tid] += red[tid + s]; __syncthreads(); }
    float inv = 1.f / red[0];
#pragma unroll
    for (int i = 0; i < 8; i++)
        out[BN * HN + b * TN + tid + i * 256] = loc[i] * inv;
}

// =================== kernel 3: context[b][col] = sum_t w[b][t] * values[b][t][col] ===================
// grid (32, 32): 32-col chunk x batch; 256 thr = 32 cols x 8 T-slices -> 1024 blocks.
__global__ void __launch_bounds__(256) context_kernel(const float* __restrict__ values,
                                                      float* __restrict__ out) {
    __shared__ float ws[TN];
    __shared__ float part[8][32];
    int b = blockIdx.y;
    int tid = threadIdx.x, tc = tid & 31, tq = tid >> 5;
    int col = blockIdx.x * 32 + tc;
    for (int i = tid; i < TN; i += 256) ws[i] = out[BN * HN + b * TN + i];
    __syncthreads();
    const float* vp = values + ((size_t)b * TN + tq * 256) * HN + col;
    float acc = 0.f;
#pragma unroll 16
    for (int t = 0; t < 256; t++)
        acc = fmaf(ws[tq * 256 + t], vp[(size_t)t * HN], acc);
    part[tq][tc] = acc;
    __syncthreads();
    if (tq == 0) {
        float s = 0.f;
#pragma unroll
        for (int i = 0; i < 8; i++) s += part[i][tc];
        out[b * HN + col] = s;
    }
}

// =================== launch ===================
extern "C" void kernel_launch(void* const* d_in, const int* in_sizes, int n_in,
                              void* d_out, int out_size) {
    const float* q      = (const float*)d_in[0];   // (1,32,1024)
    const float* values = (const float*)d_in[1];   // (32,2048,1024)
    const float* Ww     = (const float*)d_in[2];   // (1024,2048)
    const float* Wb     = (const float*)d_in[3];   // (1024,)
    const float* Vw     = (const float*)d_in[4];   // (1,1024)
    // d_in[5] = V_b : softmax-invariant, unused
    float* out = (float*)d_out;                    // [context 32*1024 | weights 32*2048]

    qbias_kernel<<<128, 256>>>(q, Ww, Wb);

    cudaFuncSetAttribute(gemm_score_kernel,
                         cudaFuncAttributeMaxDynamicSharedMemorySize, SMEM_BYTES);
    gemm_score_kernel<<<512, 256, SMEM_BYTES>>>(values, Ww, Vw);

    softmax_kernel<<<32, 256>>>(out);

    context_kernel<<<dim3(32, 32), 256>>>(values, out);
}

// round 5
// speedup vs baseline: 1.6592x; 1.4676x over previous
#include <cuda_runtime.h>
#include <cuda_fp16.h>
#include <cstdint>

// ---------------- problem constants ----------------
#define BN 32
#define TN 2048
#define HN 1024
#define UN 1024

// ---------------- device scratch (no cudaMalloc allowed) ----------------
__device__ float  g_qbias[BN * UN];          // q@Wq^T + W_b (fp32, exact)
__device__ float  g_score[BN * TN];          // pre-softmax scores
__device__ __half g_vf16[BN * TN * HN];      // values in fp16 (128MB)
__device__ __half g_wv16[UN * HN];           // Wv = W_w[:, :H] in fp16 (2MB)

// ---------------- helpers ----------------
__device__ __forceinline__ uint32_t smem_u32(const void* p) {
    uint32_t a;
    asm("{ .reg .u64 t; cvta.to.shared.u64 t, %1; cvt.u32.u64 %0, t; }" : "=r"(a) : "l"(p));
    return a;
}
__device__ __forceinline__ void mma16(float* d, const uint32_t* a, uint32_t b0, uint32_t b1) {
    asm volatile(
        "mma.sync.aligned.m16n8k16.row.col.f32.f16.f16.f32 "
        "{%0,%1,%2,%3}, {%4,%5,%6,%7}, {%8,%9}, {%0,%1,%2,%3};"
        : "+f"(d[0]), "+f"(d[1]), "+f"(d[2]), "+f"(d[3])
        : "r"(a[0]), "r"(a[1]), "r"(a[2]), "r"(a[3]), "r"(b0), "r"(b1));
}
__device__ __forceinline__ void ldsm4(uint32_t* r, uint32_t addr) {
    asm volatile("ldmatrix.sync.aligned.m8n8.x4.shared.b16 {%0,%1,%2,%3}, [%4];"
        : "=r"(r[0]), "=r"(r[1]), "=r"(r[2]), "=r"(r[3]) : "r"(addr));
}
#define CP16(dst, src) \
    asm volatile("cp.async.cg.shared.global [%0], [%1], 16;" :: "r"(dst), "l"(src))

// ---------------- gemm smem layout (bytes) ----------------
// Row = 64 data halves + 8 pad = 72 halves = 144B (ldmatrix conflict-free).
// Stage: A 128x144B + B 256x144B. 3 stages.
#define LDB_B   144u
#define STG_A_B 18432u
#define STG_B   55296u
#define OFF_QB_F 41472   // float index: 3*STG_B/4
#define OFF_VW_F 41728
#define OFF_SC_F 41984
#define SMEM_BYTES 169984

// =================== conversion kernels ===================
__global__ void __launch_bounds__(256) cvt_values_kernel(const float* __restrict__ src) {
    int i = blockIdx.x * 256 + threadIdx.x;
    const int stride = gridDim.x * 256;
    const int n8 = BN * TN * HN / 8;
    for (; i < n8; i += stride) {
        float4 f0 = ((const float4*)src)[2 * i];
        float4 f1 = ((const float4*)src)[2 * i + 1];
        __half2 h0 = __floats2half2_rn(f0.x, f0.y);
        __half2 h1 = __floats2half2_rn(f0.z, f0.w);
        __half2 h2 = __floats2half2_rn(f1.x, f1.y);
        __half2 h3 = __floats2half2_rn(f1.z, f1.w);
        uint4 u;
        u.x = *reinterpret_cast<unsigned*>(&h0);
        u.y = *reinterpret_cast<unsigned*>(&h1);
        u.z = *reinterpret_cast<unsigned*>(&h2);
        u.w = *reinterpret_cast<unsigned*>(&h3);
        reinterpret_cast<uint4*>(g_vf16)[i] = u;
    }
}
__global__ void __launch_bounds__(256) cvt_wv_kernel(const float* __restrict__ W) {
    // Wv = W_w[:, :HN]; row stride 2*HN
    int i = blockIdx.x * 256 + threadIdx.x;            // one per 8 elems; 131072 total
    int u = i >> 7, c8 = i & 127;                      // 128 8-elem chunks per row
    const float4* s = (const float4*)(W + (size_t)u * (2 * HN) + c8 * 8);
    float4 f0 = s[0], f1 = s[1];
    __half2 h0 = __floats2half2_rn(f0.x, f0.y);
    __half2 h1 = __floats2half2_rn(f0.z, f0.w);
    __half2 h2 = __floats2half2_rn(f1.x, f1.y);
    __half2 h3 = __floats2half2_rn(f1.z, f1.w);
    uint4 v;
    v.x = *reinterpret_cast<unsigned*>(&h0);
    v.y = *reinterpret_cast<unsigned*>(&h1);
    v.z = *reinterpret_cast<unsigned*>(&h2);
    v.w = *reinterpret_cast<unsigned*>(&h3);
    reinterpret_cast<uint4*>(g_wv16)[i] = v;
}

// =================== kernel 0: qbias[b][u] = q[b] . Wq[u] + W_b[u] (fp32) ===================
__global__ void __launch_bounds__(256) qbias_kernel(const float* __restrict__ q,
                                                    const float* __restrict__ W,
                                                    const float* __restrict__ Wb) {
    int tid = threadIdx.x, lane = tid & 31, w = tid >> 5;
    int u = blockIdx.x * 8 + w;
    const float* wrow = W + (size_t)u * (2 * HN) + HN;   // Wq = W_w[:, H:]
    float wreg[32];
#pragma unroll
    for (int i = 0; i < 32; i++) wreg[i] = wrow[lane + i * 32];
    float wb = Wb[u];
    for (int b = 0; b < BN; b++) {
        const float* qb = q + b * HN;
        float acc = 0.f;
#pragma unroll
        for (int i = 0; i < 32; i++) acc = fmaf(wreg[i], qb[lane + i * 32], acc);
#pragma unroll
        for (int o = 16; o; o >>= 1) acc += __shfl_xor_sync(0xFFFFFFFFu, acc, o);
        if (lane == 0) g_qbias[b * UN + u] = acc + wb;
    }
}

// =================== kernel 1: fused fp16 GEMM + tanh reduce ===================
// 256 thr, 8 warps (2M x 4N), warp tile 64x64, mma.m16n8k16.f16.f32.
// CTA tile M=128 x N=256, 4 sequential N-quarters. K-slab 64, 3-stage cp.async.
__global__ void __launch_bounds__(256, 1)
gemm_score_kernel(const float* __restrict__ Vw) {
    extern __shared__ float sm[];
    const uint32_t sbase = smem_u32(sm);
    const int tid = threadIdx.x;
    const int lane = tid & 31, wid = tid >> 5;
    const int wm = wid & 1, wn = wid >> 1;
    const size_t m0 = (size_t)blockIdx.x * 128;
    const int b = blockIdx.x >> 4;                 // 16 M-tiles per batch

    sm[OFF_SC_F + tid] = 0.f;
    sm[OFF_SC_F + 256 + tid] = 0.f;

    // per-lane ldmatrix byte offsets within a stage
    // A frag (16x16): rows lane&15, k-block lane>>4
    const uint32_t a_lane =
        (uint32_t)((wm * 64 + (lane & 15)) * LDB_B + (lane >> 4) * 16);
    // B frag (16n x 16k): rows n = ((lane>>4)&1)*8 + (lane&7), k-block (lane>>3)&1
    const uint32_t b_lane =
        (uint32_t)(STG_A_B + (wn * 64 + ((lane >> 4) & 1) * 8 + (lane & 7)) * LDB_B +
                   ((lane >> 3) & 1) * 16);

    auto load_slab = [&](int ks, int stg, int u0) {
        const int k0 = ks * 64;
        const uint32_t ab = sbase + (uint32_t)stg * STG_B;
        const uint32_t bb = ab + STG_A_B;
#pragma unroll
        for (int i = 0; i < 4; i++) {               // A: 128 rows x 8 16B-chunks
            int idx = tid + i * 256;
            int row = idx >> 3, c = idx & 7;
            CP16(ab + (uint32_t)row * LDB_B + c * 16,
                 g_vf16 + (m0 + row) * HN + k0 + c * 8);
        }
#pragma unroll
        for (int i = 0; i < 8; i++) {               // B: 256 rows x 8 16B-chunks
            int idx = tid + i * 256;
            int row = idx >> 3, c = idx & 7;
            CP16(bb + (uint32_t)row * LDB_B + c * 16,
                 g_wv16 + (size_t)(u0 + row) * HN + k0 + c * 8);
        }
        asm volatile("cp.async.commit_group;" ::: "memory");
    };

    float acc[4][8][4];

    for (int nt = 0; nt < 4; nt++) {
        const int u0 = nt * 256;
        sm[OFF_QB_F + tid] = g_qbias[b * UN + u0 + tid];
        sm[OFF_VW_F + tid] = Vw[u0 + tid];
#pragma unroll
        for (int i = 0; i < 4; i++)
#pragma unroll
            for (int j = 0; j < 8; j++)
#pragma unroll
                for (int k = 0; k < 4; k++) acc[i][j][k] = 0.f;

        load_slab(0, 0, u0);
        load_slab(1, 1, u0);

        for (int ks = 0; ks < 16; ks++) {
            asm volatile("cp.async.wait_group 1;" ::: "memory");
            __syncthreads();
            if (ks + 2 < 16) load_slab(ks + 2, (ks + 2) % 3, u0);
            else asm volatile("cp.async.commit_group;" ::: "memory");

            const uint32_t stg_base = sbase + (uint32_t)((ks % 3) * STG_B);
            const uint32_t abase = stg_base + a_lane;
            const uint32_t bbase = stg_base + b_lane;
#pragma unroll
            for (int kk = 0; kk < 4; kk++) {        // 4 x k16
                const uint32_t kb = kk * 32;        // 16 halves = 32B
                uint32_t af[4][4], bf[4][4];
#pragma unroll
                for (int ms = 0; ms < 4; ms++)
                    ldsm4(af[ms], abase + ms * (16 * LDB_B) + kb);
#pragma unroll
                for (int j = 0; j < 4; j++)
                    ldsm4(bf[j], bbase + j * (16 * LDB_B) + kb);
#pragma unroll
                for (int ms = 0; ms < 4; ms++)
#pragma unroll
                    for (int j = 0; j < 4; j++) {
                        mma16(acc[ms][2 * j],     af[ms], bf[j][0], bf[j][1]);
                        mma16(acc[ms][2 * j + 1], af[ms], bf[j][2], bf[j][3]);
                    }
            }
        }

        // ---- epilogue: rsum[row] += tanh(acc + qbias) * Vw ----
        float rsum[4][2];
#pragma unroll
        for (int ms = 0; ms < 4; ms++) { rsum[ms][0] = 0.f; rsum[ms][1] = 0.f; }
#pragma unroll
        for (int ms = 0; ms < 4; ms++)
#pragma unroll
            for (int ns = 0; ns < 8; ns++)
#pragma unroll
                for (int d = 0; d < 4; d++) {
                    int col = wn * 64 + ns * 8 + (lane & 3) * 2 + (d & 1);
                    float x = acc[ms][ns][d] + sm[OFF_QB_F + col];
                    float e = __expf(x + x);
                    float th = 1.f - 2.f / (e + 1.f);   // exact tanh, stable both tails
                    rsum[ms][d >> 1] = fmaf(th, sm[OFF_VW_F + col], rsum[ms][d >> 1]);
                }
#pragma unroll
        for (int ms = 0; ms < 4; ms++)
#pragma unroll
            for (int hi = 0; hi < 2; hi++) {
                float v = rsum[ms][hi];
                v += __shfl_xor_sync(0xFFFFFFFFu, v, 1);
                v += __shfl_xor_sync(0xFFFFFFFFu, v, 2);
                if ((lane & 3) == 0) {
                    int row = wm * 64 + ms * 16 + hi * 8 + (lane >> 2);
                    sm[OFF_SC_F + row * 4 + wn] += v;   // unique (row, wn) writer
                }
            }
        __syncthreads();
    }

    if (tid < 128)
        g_score[m0 + tid] = sm[OFF_SC_F + tid * 4] + sm[OFF_SC_F + tid * 4 + 1] +
                            sm[OFF_SC_F + tid * 4 + 2] + sm[OFF_SC_F + tid * 4 + 3];
}

// =================== kernel 2: softmax over T per batch ===================
__global__ void __launch_bounds__(256) softmax_kernel(float* __restrict__ out) {
    __shared__ float red[256];
    int b = blockIdx.x, tid = threadIdx.x;
    float loc[8];
    float mx = -1e30f;
#pragma unroll
    for (int i = 0; i < 8; i++) {
        loc[i] = g_score[b * TN + tid + i * 256];
        mx = fmaxf(mx, loc[i]);
    }
    red[tid] = mx; __syncthreads();
    for (int s = 128; s; s >>= 1) { if (tid < s) red[tid] = fmaxf(red[tid], red[tid + s]); __syncthreads(); }
    float m = red[0]; __syncthreads();
    float sum = 0.f;
#pragma unroll
    for (int i = 0; i < 8; i++) { loc[i] = __expf(loc[i] - m); sum += loc[i]; }
    red[tid] = sum; __syncthreads();
    for (int s = 128; s; s >>= 1) { if (tid < s) red[tid] += red[tid + s]; __syncthreads(); }
    float inv = 1.f / red[0];
#pragma unroll
    for (int i = 0; i < 8; i++)
        out[BN * HN + b * TN + tid + i * 256] = loc[i] * inv;
}

// =================== kernel 3: context[b][col] = sum_t w[b][t] * values[b][t][col] ===================
__global__ void __launch_bounds__(256) context_kernel(const float* __restrict__ values,
                                                      float* __restrict__ out) {
    __shared__ float ws[TN];
    __shared__ float part[8][32];
    int b = blockIdx.y;
    int tid = threadIdx.x, tc = tid & 31, tq = tid >> 5;
    int col = blockIdx.x * 32 + tc;
    for (int i = tid; i < TN; i += 256) ws[i] = out[BN * HN + b * TN + i];
    __syncthreads();
    const float* vp = values + ((size_t)b * TN + tq * 256) * HN + col;
    float acc = 0.f;
#pragma unroll 16
    for (int t = 0; t < 256; t++)
        acc = fmaf(ws[tq * 256 + t], vp[(size_t)t * HN], acc);
    part[tq][tc] = acc;
    __syncthreads();
    if (tq == 0) {
        float s = 0.f;
#pragma unroll
        for (int i = 0; i < 8; i++) s += part[i][tc];
        out[b * HN + col] = s;
    }
}

// =================== launch ===================
extern "C" void kernel_launch(void* const* d_in, const int* in_sizes, int n_in,
                              void* d_out, int out_size) {
    const float* q      = (const float*)d_in[0];   // (1,32,1024)
    const float* values = (const float*)d_in[1];   // (32,2048,1024)
    const float* Ww     = (const float*)d_in[2];   // (1024,2048)
    const float* Wb     = (const float*)d_in[3];   // (1024,)
    const float* Vw     = (const float*)d_in[4];   // (1,1024)
    // d_in[5] = V_b : softmax-invariant, unused
    float* out = (float*)d_out;                    // [context 32*1024 | weights 32*2048]

    cvt_values_kernel<<<2048, 256>>>(values);
    cvt_wv_kernel<<<512, 256>>>(Ww);
    qbias_kernel<<<128, 256>>>(q, Ww, Wb);

    cudaFuncSetAttribute(gemm_score_kernel,
                         cudaFuncAttributeMaxDynamicSharedMemorySize, SMEM_BYTES);
    gemm_score_kernel<<<512, 256, SMEM_BYTES>>>(Vw);

    softmax_kernel<<<32, 256>>>(out);

    context_kernel<<<dim3(32, 32), 256>>>(values, out);
}

// round 6
// speedup vs baseline: 1.8414x; 1.1098x over previous
#include <cuda_runtime.h>
#include <cuda_fp16.h>
#include <cstdint>

// ---------------- problem constants ----------------
#define BN 32
#define TN 2048
#define HN 1024
#define UN 1024

// ---------------- device scratch (no cudaMalloc allowed) ----------------
__device__ float  g_qbias[BN * UN];          // q@Wq^T + W_b (fp32, exact)
__device__ float  g_score[BN * TN];          // pre-softmax scores
__device__ __half g_vf16[BN * TN * HN];      // values in fp16 (128MB)
__device__ __half g_wv16[UN * HN];           // Wv = W_w[:, :H] in fp16 (2MB)

// ---------------- helpers ----------------
__device__ __forceinline__ uint32_t smem_u32(const void* p) {
    uint32_t a;
    asm("{ .reg .u64 t; cvta.to.shared.u64 t, %1; cvt.u32.u64 %0, t; }" : "=r"(a) : "l"(p));
    return a;
}
__device__ __forceinline__ void mma16(float* d, const uint32_t* a, uint32_t b0, uint32_t b1) {
    asm volatile(
        "mma.sync.aligned.m16n8k16.row.col.f32.f16.f16.f32 "
        "{%0,%1,%2,%3}, {%4,%5,%6,%7}, {%8,%9}, {%0,%1,%2,%3};"
        : "+f"(d[0]), "+f"(d[1]), "+f"(d[2]), "+f"(d[3])
        : "r"(a[0]), "r"(a[1]), "r"(a[2]), "r"(a[3]), "r"(b0), "r"(b1));
}
__device__ __forceinline__ void ldsm4(uint32_t* r, uint32_t addr) {
    asm volatile("ldmatrix.sync.aligned.m8n8.x4.shared.b16 {%0,%1,%2,%3}, [%4];"
        : "=r"(r[0]), "=r"(r[1]), "=r"(r[2]), "=r"(r[3]) : "r"(addr));
}
#define CP16(dst, src) \
    asm volatile("cp.async.cg.shared.global [%0], [%1], 16;" :: "r"(dst), "l"(src))

// ---------------- gemm smem layout (bytes) ----------------
// Row = 64 data halves + 8 pad = 72 halves = 144B (ldmatrix conflict-free).
// Stage: A 128x144B + B 256x144B. 3 stages.
#define LDB_B   144u
#define STG_A_B 18432u
#define STG_B   55296u
#define OFF_QB_F 41472   // float index: 3*STG_B/4
#define OFF_VW_F 41728
#define OFF_SC_F 41984
#define SMEM_BYTES 169984

// =================== conversion kernels ===================
__global__ void __launch_bounds__(256) cvt_values_kernel(const float* __restrict__ src) {
    int i = blockIdx.x * 256 + threadIdx.x;
    const int stride = gridDim.x * 256;
    const int n8 = BN * TN * HN / 8;
    for (; i < n8; i += stride) {
        float4 f0 = ((const float4*)src)[2 * i];
        float4 f1 = ((const float4*)src)[2 * i + 1];
        __half2 h0 = __floats2half2_rn(f0.x, f0.y);
        __half2 h1 = __floats2half2_rn(f0.z, f0.w);
        __half2 h2 = __floats2half2_rn(f1.x, f1.y);
        __half2 h3 = __floats2half2_rn(f1.z, f1.w);
        uint4 u;
        u.x = *reinterpret_cast<unsigned*>(&h0);
        u.y = *reinterpret_cast<unsigned*>(&h1);
        u.z = *reinterpret_cast<unsigned*>(&h2);
        u.w = *reinterpret_cast<unsigned*>(&h3);
        reinterpret_cast<uint4*>(g_vf16)[i] = u;
    }
}
__global__ void __launch_bounds__(256) cvt_wv_kernel(const float* __restrict__ W) {
    // Wv = W_w[:, :HN]; row stride 2*HN
    int i = blockIdx.x * 256 + threadIdx.x;            // one per 8 elems; 131072 total
    int u = i >> 7, c8 = i & 127;
    const float4* s = (const float4*)(W + (size_t)u * (2 * HN) + c8 * 8);
    float4 f0 = s[0], f1 = s[1];
    __half2 h0 = __floats2half2_rn(f0.x, f0.y);
    __half2 h1 = __floats2half2_rn(f0.z, f0.w);
    __half2 h2 = __floats2half2_rn(f1.x, f1.y);
    __half2 h3 = __floats2half2_rn(f1.z, f1.w);
    uint4 v;
    v.x = *reinterpret_cast<unsigned*>(&h0);
    v.y = *reinterpret_cast<unsigned*>(&h1);
    v.z = *reinterpret_cast<unsigned*>(&h2);
    v.w = *reinterpret_cast<unsigned*>(&h3);
    reinterpret_cast<uint4*>(g_wv16)[i] = v;
}

// =================== kernel 0: qbias[b][u] = q[b] . Wq[u] + W_b[u] (fp32) ===================
__global__ void __launch_bounds__(256) qbias_kernel(const float* __restrict__ q,
                                                    const float* __restrict__ W,
                                                    const float* __restrict__ Wb) {
    int tid = threadIdx.x, lane = tid & 31, w = tid >> 5;
    int u = blockIdx.x * 8 + w;
    const float* wrow = W + (size_t)u * (2 * HN) + HN;   // Wq = W_w[:, H:]
    float wreg[32];
#pragma unroll
    for (int i = 0; i < 32; i++) wreg[i] = wrow[lane + i * 32];
    float wb = Wb[u];
    for (int b = 0; b < BN; b++) {
        const float* qb = q + b * HN;
        float acc = 0.f;
#pragma unroll
        for (int i = 0; i < 32; i++) acc = fmaf(wreg[i], qb[lane + i * 32], acc);
#pragma unroll
        for (int o = 16; o; o >>= 1) acc += __shfl_xor_sync(0xFFFFFFFFu, acc, o);
        if (lane == 0) g_qbias[b * UN + u] = acc + wb;
    }
}

// =================== kernel 1: fused fp16 GEMM + tanh reduce ===================
// 512 thr, 16 warps (4M x 4N), warp tile 32x64, mma.m16n8k16.f16.f32.
// CTA tile M=128 x N=256, 4 sequential N-quarters. K-slab 64, 3-stage cp.async.
__global__ void __launch_bounds__(512, 1)
gemm_score_kernel(const float* __restrict__ Vw) {
    extern __shared__ float sm[];
    const uint32_t sbase = smem_u32(sm);
    const int tid = threadIdx.x;
    const int lane = tid & 31, wid = tid >> 5;
    const int wm = wid & 3, wn = wid >> 2;
    const size_t m0 = (size_t)blockIdx.x * 128;
    const int b = blockIdx.x >> 4;                 // 16 M-tiles per batch

    sm[OFF_SC_F + tid] = 0.f;                      // 512 score partials (128 rows x 4 wn)

    // per-lane ldmatrix byte offsets within a stage
    const uint32_t a_lane =
        (uint32_t)((wm * 32 + (lane & 15)) * LDB_B + (lane >> 4) * 16);
    const uint32_t b_lane =
        (uint32_t)(STG_A_B + (wn * 64 + ((lane >> 4) & 1) * 8 + (lane & 7)) * LDB_B +
                   ((lane >> 3) & 1) * 16);

    auto load_slab = [&](int ks, int stg, int u0) {
        const int k0 = ks * 64;
        const uint32_t ab = sbase + (uint32_t)stg * STG_B;
        const uint32_t bb = ab + STG_A_B;
#pragma unroll
        for (int i = 0; i < 2; i++) {               // A: 128 rows x 8 16B-chunks
            int idx = tid + i * 512;
            int row = idx >> 3, c = idx & 7;
            CP16(ab + (uint32_t)row * LDB_B + c * 16,
                 g_vf16 + (m0 + row) * HN + k0 + c * 8);
        }
#pragma unroll
        for (int i = 0; i < 4; i++) {               // B: 256 rows x 8 16B-chunks
            int idx = tid + i * 512;
            int row = idx >> 3, c = idx & 7;
            CP16(bb + (uint32_t)row * LDB_B + c * 16,
                 g_wv16 + (size_t)(u0 + row) * HN + k0 + c * 8);
        }
        asm volatile("cp.async.commit_group;" ::: "memory");
    };

    float acc[2][8][4];

    for (int nt = 0; nt < 4; nt++) {
        const int u0 = nt * 256;
        if (tid < 256) {
            sm[OFF_QB_F + tid] = g_qbias[b * UN + u0 + tid];
            sm[OFF_VW_F + tid] = Vw[u0 + tid];
        }
#pragma unroll
        for (int i = 0; i < 2; i++)
#pragma unroll
            for (int j = 0; j < 8; j++)
#pragma unroll
                for (int k = 0; k < 4; k++) acc[i][j][k] = 0.f;

        load_slab(0, 0, u0);
        load_slab(1, 1, u0);

        for (int ks = 0; ks < 16; ks++) {
            asm volatile("cp.async.wait_group 1;" ::: "memory");
            __syncthreads();
            if (ks + 2 < 16) load_slab(ks + 2, (ks + 2) % 3, u0);
            else asm volatile("cp.async.commit_group;" ::: "memory");

            const uint32_t stg_base = sbase + (uint32_t)((ks % 3) * STG_B);
            const uint32_t abase = stg_base + a_lane;
            const uint32_t bbase = stg_base + b_lane;
#pragma unroll
            for (int kk = 0; kk < 4; kk++) {        // 4 x k16
                const uint32_t kb = kk * 32;        // 16 halves = 32B
                uint32_t af[2][4], bf[4][4];
#pragma unroll
                for (int ms = 0; ms < 2; ms++)
                    ldsm4(af[ms], abase + ms * (16 * LDB_B) + kb);
#pragma unroll
                for (int j = 0; j < 4; j++)
                    ldsm4(bf[j], bbase + j * (16 * LDB_B) + kb);
#pragma unroll
                for (int ms = 0; ms < 2; ms++)
#pragma unroll
                    for (int j = 0; j < 4; j++) {
                        mma16(acc[ms][2 * j],     af[ms], bf[j][0], bf[j][1]);
                        mma16(acc[ms][2 * j + 1], af[ms], bf[j][2], bf[j][3]);
                    }
            }
        }

        // ---- epilogue: rsum[row] += tanh(acc + qbias) * Vw ----
        float rsum[2][2];
#pragma unroll
        for (int ms = 0; ms < 2; ms++) { rsum[ms][0] = 0.f; rsum[ms][1] = 0.f; }
#pragma unroll
        for (int ms = 0; ms < 2; ms++)
#pragma unroll
            for (int ns = 0; ns < 8; ns++)
#pragma unroll
                for (int d = 0; d < 4; d++) {
                    int col = wn * 64 + ns * 8 + (lane & 3) * 2 + (d & 1);
                    float x = acc[ms][ns][d] + sm[OFF_QB_F + col];
                    float e = __expf(x + x);
                    float th = 1.f - 2.f / (e + 1.f);   // exact tanh, stable both tails
                    rsum[ms][d >> 1] = fmaf(th, sm[OFF_VW_F + col], rsum[ms][d >> 1]);
                }
#pragma unroll
        for (int ms = 0; ms < 2; ms++)
#pragma unroll
            for (int hi = 0; hi < 2; hi++) {
                float v = rsum[ms][hi];
                v += __shfl_xor_sync(0xFFFFFFFFu, v, 1);
                v += __shfl_xor_sync(0xFFFFFFFFu, v, 2);
                if ((lane & 3) == 0) {
                    int row = wm * 32 + ms * 16 + hi * 8 + (lane >> 2);
                    sm[OFF_SC_F + row * 4 + wn] += v;   // unique (row, wn) writer
                }
            }
        __syncthreads();
    }

    if (tid < 128)
        g_score[m0 + tid] = sm[OFF_SC_F + tid * 4] + sm[OFF_SC_F + tid * 4 + 1] +
                            sm[OFF_SC_F + tid * 4 + 2] + sm[OFF_SC_F + tid * 4 + 3];
}

// =================== kernel 2: softmax over T per batch ===================
__global__ void __launch_bounds__(256) softmax_kernel(float* __restrict__ out) {
    __shared__ float red[256];
    int b = blockIdx.x, tid = threadIdx.x;
    float loc[8];
    float mx = -1e30f;
#pragma unroll
    for (int i = 0; i < 8; i++) {
        loc[i] = g_score[b * TN + tid + i * 256];
        mx = fmaxf(mx, loc[i]);
    }
    red[tid] = mx; __syncthreads();
    for (int s = 128; s; s >>= 1) { if (tid < s) red[tid] = fmaxf(red[tid], red[tid + s]); __syncthreads(); }
    float m = red[0]; __syncthreads();
    float sum = 0.f;
#pragma unroll
    for (int i = 0; i < 8; i++) { loc[i] = __expf(loc[i] - m); sum += loc[i]; }
    red[tid] = sum; __syncthreads();
    for (int s = 128; s; s >>= 1) { if (tid < s) red[tid] += red[tid + s]; __syncthreads(); }
    float inv = 1.f / red[0];
#pragma unroll
    for (int i = 0; i < 8; i++)
        out[BN * HN + b * TN + tid + i * 256] = loc[i] * inv;
}

// =================== kernel 3: context from fp16 values ===================
// grid (16, 32): 64-col chunk x batch; 256 thr = 64 cols x 4 T-slices.
__global__ void __launch_bounds__(256) context_kernel(float* __restrict__ out) {
    __shared__ float ws[TN];
    __shared__ float part[4][64];
    int b = blockIdx.y;
    int tid = threadIdx.x, tc = tid & 63, tq = tid >> 6;
    int col = blockIdx.x * 64 + tc;
    for (int i = tid; i < TN; i += 256) ws[i] = out[BN * HN + b * TN + i];
    __syncthreads();
    const __half* vp = g_vf16 + ((size_t)b * TN + tq * 512) * HN + col;
    float acc = 0.f;
#pragma unroll 16
    for (int t = 0; t < 512; t++)
        acc = fmaf(ws[tq * 512 + t], __half2float(vp[(size_t)t * HN]), acc);
    part[tq][tc] = acc;
    __syncthreads();
    if (tq == 0)
        out[b * HN + col] = part[0][tc] + part[1][tc] + part[2][tc] + part[3][tc];
}

// =================== launch ===================
extern "C" void kernel_launch(void* const* d_in, const int* in_sizes, int n_in,
                              void* d_out, int out_size) {
    const float* q      = (const float*)d_in[0];   // (1,32,1024)
    const float* values = (const float*)d_in[1];   // (32,2048,1024)
    const float* Ww     = (const float*)d_in[2];   // (1024,2048)
    const float* Wb     = (const float*)d_in[3];   // (1024,)
    const float* Vw     = (const float*)d_in[4];   // (1,1024)
    // d_in[5] = V_b : softmax-invariant, unused
    float* out = (float*)d_out;                    // [context 32*1024 | weights 32*2048]

    cvt_values_kernel<<<2048, 256>>>(values);
    cvt_wv_kernel<<<512, 256>>>(Ww);
    qbias_kernel<<<128, 256>>>(q, Ww, Wb);

    cudaFuncSetAttribute(gemm_score_kernel,
                         cudaFuncAttributeMaxDynamicSharedMemorySize, SMEM_BYTES);
    gemm_score_kernel<<<512, 512, SMEM_BYTES>>>(Vw);

    softmax_kernel<<<32, 256>>>(out);

    context_kernel<<<dim3(16, 32), 256>>>(out);
}

// round 7
// speedup vs baseline: 2.0332x; 1.1042x over previous
#include <cuda_runtime.h>
#include <cuda_fp16.h>
#include <cstdint>

// ---------------- problem constants ----------------
#define BN 32
#define TN 2048
#define HN 1024
#define UN 1024

// ---------------- device scratch (no cudaMalloc allowed) ----------------
__device__ float  g_qbias[BN * UN];          // q@Wq^T + W_b (fp32, exact)
__device__ float  g_score[BN * TN];          // pre-softmax scores
__device__ __half g_vf16[BN * TN * HN];      // values in fp16 (128MB)
__device__ __half g_wv16[UN * HN];           // Wv = W_w[:, :H] in fp16 (2MB)

// ---------------- helpers ----------------
__device__ __forceinline__ uint32_t smem_u32(const void* p) {
    uint32_t a;
    asm("{ .reg .u64 t; cvta.to.shared.u64 t, %1; cvt.u32.u64 %0, t; }" : "=r"(a) : "l"(p));
    return a;
}
__device__ __forceinline__ void mma16(float* d, const uint32_t* a, uint32_t b0, uint32_t b1) {
    asm volatile(
        "mma.sync.aligned.m16n8k16.row.col.f32.f16.f16.f32 "
        "{%0,%1,%2,%3}, {%4,%5,%6,%7}, {%8,%9}, {%0,%1,%2,%3};"
        : "+f"(d[0]), "+f"(d[1]), "+f"(d[2]), "+f"(d[3])
        : "r"(a[0]), "r"(a[1]), "r"(a[2]), "r"(a[3]), "r"(b0), "r"(b1));
}
__device__ __forceinline__ void ldsm4(uint32_t* r, uint32_t addr) {
    asm volatile("ldmatrix.sync.aligned.m8n8.x4.shared.b16 {%0,%1,%2,%3}, [%4];"
        : "=r"(r[0]), "=r"(r[1]), "=r"(r[2]), "=r"(r[3]) : "r"(addr));
}
#define CP16(dst, src) \
    asm volatile("cp.async.cg.shared.global [%0], [%1], 16;" :: "r"(dst), "l"(src))

// ---------------- gemm smem layout ----------------
// Stage (96KB): A = 2 sections x [128 rows x 128B], B (+32KB) = 2 sections x [256 x 128B].
// XOR swizzle within a row: chunk(16B) index c stored at (c ^ (row&7)).
// K-slab 128: section s = k64-half, chunk c = (k%64)/8.
#define STG_BYTES 98304u
#define OFF_QB_F 49152   // = 2*STG_BYTES/4
#define OFF_VW_F 49408
#define OFF_SC_F 49664
#define SMEM_BYTES 200704

// =================== conversion kernels ===================
__global__ void __launch_bounds__(256) cvt_values_kernel(const float* __restrict__ src) {
    int i = blockIdx.x * 256 + threadIdx.x;
    const int stride = gridDim.x * 256;
    const int n8 = BN * TN * HN / 8;
    for (; i < n8; i += stride) {
        float4 f0 = ((const float4*)src)[2 * i];
        float4 f1 = ((const float4*)src)[2 * i + 1];
        __half2 h0 = __floats2half2_rn(f0.x, f0.y);
        __half2 h1 = __floats2half2_rn(f0.z, f0.w);
        __half2 h2 = __floats2half2_rn(f1.x, f1.y);
        __half2 h3 = __floats2half2_rn(f1.z, f1.w);
        uint4 u;
        u.x = *reinterpret_cast<unsigned*>(&h0);
        u.y = *reinterpret_cast<unsigned*>(&h1);
        u.z = *reinterpret_cast<unsigned*>(&h2);
        u.w = *reinterpret_cast<unsigned*>(&h3);
        reinterpret_cast<uint4*>(g_vf16)[i] = u;
    }
}
__global__ void __launch_bounds__(256) cvt_wv_kernel(const float* __restrict__ W) {
    // Wv = W_w[:, :HN]; row stride 2*HN
    int i = blockIdx.x * 256 + threadIdx.x;            // one per 8 elems; 131072 total
    int u = i >> 7, c8 = i & 127;
    const float4* s = (const float4*)(W + (size_t)u * (2 * HN) + c8 * 8);
    float4 f0 = s[0], f1 = s[1];
    __half2 h0 = __floats2half2_rn(f0.x, f0.y);
    __half2 h1 = __floats2half2_rn(f0.z, f0.w);
    __half2 h2 = __floats2half2_rn(f1.x, f1.y);
    __half2 h3 = __floats2half2_rn(f1.z, f1.w);
    uint4 v;
    v.x = *reinterpret_cast<unsigned*>(&h0);
    v.y = *reinterpret_cast<unsigned*>(&h1);
    v.z = *reinterpret_cast<unsigned*>(&h2);
    v.w = *reinterpret_cast<unsigned*>(&h3);
    reinterpret_cast<uint4*>(g_wv16)[i] = v;
}

// =================== kernel 0: qbias[b][u] = q[b] . Wq[u] + W_b[u] (fp32) ===================
__global__ void __launch_bounds__(256) qbias_kernel(const float* __restrict__ q,
                                                    const float* __restrict__ W,
                                                    const float* __restrict__ Wb) {
    int tid = threadIdx.x, lane = tid & 31, w = tid >> 5;
    int u = blockIdx.x * 8 + w;
    const float* wrow = W + (size_t)u * (2 * HN) + HN;   // Wq = W_w[:, H:]
    float wreg[32];
#pragma unroll
    for (int i = 0; i < 32; i++) wreg[i] = wrow[lane + i * 32];
    float wb = Wb[u];
    for (int b = 0; b < BN; b++) {
        const float* qb = q + b * HN;
        float acc = 0.f;
#pragma unroll
        for (int i = 0; i < 32; i++) acc = fmaf(wreg[i], qb[lane + i * 32], acc);
#pragma unroll
        for (int o = 16; o; o >>= 1) acc += __shfl_xor_sync(0xFFFFFFFFu, acc, o);
        if (lane == 0) g_qbias[b * UN + u] = acc + wb;
    }
}

// =================== kernel 1: fused fp16 GEMM + tanh reduce ===================
// 512 thr, 16 warps (4M x 4N), warp tile 32x64, mma.m16n8k16.f16.f32.
// CTA tile M=128 x N=256, 4 N-quarters via a single 32-slab pipeline
// (global slab counter g: nt = g>>3, k0 = (g&7)*128). 2 stages, K-slab 128.
__global__ void __launch_bounds__(512, 1)
gemm_score_kernel(const float* __restrict__ Vw) {
    extern __shared__ float sm[];
    const uint32_t sbase = smem_u32(sm);
    const int tid = threadIdx.x;
    const int lane = tid & 31, wid = tid >> 5;
    const int wm = wid & 3, wn = wid >> 2;
    const size_t m0 = (size_t)blockIdx.x * 128;
    const int b = blockIdx.x >> 4;                 // 16 M-tiles per batch

    sm[OFF_SC_F + tid] = 0.f;                      // 512 score partials (128 rows x 4 wn)
    if (tid < 256) {                               // stage quarter 0 qbias/Vw
        sm[OFF_QB_F + tid] = g_qbias[b * UN + tid];
        sm[OFF_VW_F + tid] = Vw[tid];
    }

    const int l7 = lane & 7;
    const int hiA = lane >> 4;                     // A k-chunk select
    const int hiB = (lane >> 3) & 1;               // B k-chunk select
    const uint32_t aRow = (uint32_t)(wm * 32 + (lane & 15)) * 128u;
    const uint32_t bRow = (uint32_t)(wn * 64 + ((lane >> 4) & 1) * 8 + l7) * 128u;

    auto load_slab = [&](int g) {
        const int k0 = (g & 7) * 128;
        const int u0 = (g >> 3) * 256;
        const uint32_t st = sbase + (uint32_t)(g & 1) * STG_BYTES;
#pragma unroll
        for (int i = 0; i < 4; i++) {              // A: 128 rows x 16 16B-chunks
            int idx = tid + i * 512;
            int row = idx >> 4, gc = idx & 15;
            uint32_t dst = st + (uint32_t)(gc >> 3) * 16384u + (uint32_t)row * 128u +
                           (uint32_t)(((gc & 7) ^ (row & 7)) << 4);
            CP16(dst, g_vf16 + (m0 + row) * HN + k0 + gc * 8);
        }
#pragma unroll
        for (int i = 0; i < 8; i++) {              // B: 256 rows x 16 16B-chunks
            int idx = tid + i * 512;
            int row = idx >> 4, gc = idx & 15;
            uint32_t dst = st + 32768u + (uint32_t)(gc >> 3) * 32768u +
                           (uint32_t)row * 128u +
                           (uint32_t)(((gc & 7) ^ (row & 7)) << 4);
            CP16(dst, g_wv16 + (size_t)(u0 + row) * HN + k0 + gc * 8);
        }
        asm volatile("cp.async.commit_group;" ::: "memory");
    };

    float acc[2][8][4];
#pragma unroll
    for (int i = 0; i < 2; i++)
#pragma unroll
        for (int j = 0; j < 8; j++)
#pragma unroll
            for (int k = 0; k < 4; k++) acc[i][j][k] = 0.f;

    load_slab(0);

    for (int g = 0; g < 32; g++) {
        asm volatile("cp.async.wait_group 0;" ::: "memory");
        __syncthreads();
        if (g + 1 < 32) load_slab(g + 1);

        const uint32_t st = sbase + (uint32_t)(g & 1) * STG_BYTES;
        const uint32_t aB = st + aRow;
        const uint32_t bB = st + 32768u + bRow;
#pragma unroll
        for (int kk = 0; kk < 8; kk++) {           // 8 x k16
            const uint32_t sA = (uint32_t)(kk >> 2) * 16384u;
            const uint32_t sB = (uint32_t)(kk >> 2) * 32768u;
            const int c0 = (kk & 3) * 2;
            const uint32_t swA = (uint32_t)(((c0 + hiA) ^ l7) << 4);
            const uint32_t swB = (uint32_t)(((c0 + hiB) ^ l7) << 4);
            uint32_t af[2][4], bf[4][4];
#pragma unroll
            for (int ms = 0; ms < 2; ms++)
                ldsm4(af[ms], aB + sA + (uint32_t)ms * 2048u + swA);
#pragma unroll
            for (int j = 0; j < 4; j++)
                ldsm4(bf[j], bB + sB + (uint32_t)j * 2048u + swB);
#pragma unroll
            for (int ms = 0; ms < 2; ms++)
#pragma unroll
                for (int j = 0; j < 4; j++) {
                    mma16(acc[ms][2 * j],     af[ms], bf[j][0], bf[j][1]);
                    mma16(acc[ms][2 * j + 1], af[ms], bf[j][2], bf[j][3]);
                }
        }

        if ((g & 7) == 7) {
            // ---- epilogue for quarter nt = g>>3: rsum[row] += tanh(acc+qb)*Vw ----
            float rsum[2][2];
#pragma unroll
            for (int ms = 0; ms < 2; ms++) { rsum[ms][0] = 0.f; rsum[ms][1] = 0.f; }
#pragma unroll
            for (int ms = 0; ms < 2; ms++)
#pragma unroll
                for (int ns = 0; ns < 8; ns++)
#pragma unroll
                    for (int d = 0; d < 4; d++) {
                        int col = wn * 64 + ns * 8 + (lane & 3) * 2 + (d & 1);
                        float x = acc[ms][ns][d] + sm[OFF_QB_F + col];
                        float e = __expf(x + x);
                        float th = 1.f - 2.f / (e + 1.f);   // exact tanh
                        rsum[ms][d >> 1] = fmaf(th, sm[OFF_VW_F + col], rsum[ms][d >> 1]);
                    }
#pragma unroll
            for (int ms = 0; ms < 2; ms++)
#pragma unroll
                for (int hi = 0; hi < 2; hi++) {
                    float v = rsum[ms][hi];
                    v += __shfl_xor_sync(0xFFFFFFFFu, v, 1);
                    v += __shfl_xor_sync(0xFFFFFFFFu, v, 2);
                    if ((lane & 3) == 0) {
                        int row = wm * 32 + ms * 16 + hi * 8 + (lane >> 2);
                        sm[OFF_SC_F + row * 4 + wn] += v;   // unique (row, wn) writer
                    }
                }
            __syncthreads();                        // epilogue reads done
            if (g + 1 < 32) {
                int u0n = ((g + 1) >> 3) * 256;
                if (tid < 256) {
                    sm[OFF_QB_F + tid] = g_qbias[b * UN + u0n + tid];
                    sm[OFF_VW_F + tid] = Vw[u0n + tid];
                }
            }
#pragma unroll
            for (int i = 0; i < 2; i++)
#pragma unroll
                for (int j = 0; j < 8; j++)
#pragma unroll
                    for (int k = 0; k < 4; k++) acc[i][j][k] = 0.f;
        }
    }

    if (tid < 128)
        g_score[m0 + tid] = sm[OFF_SC_F + tid * 4] + sm[OFF_SC_F + tid * 4 + 1] +
                            sm[OFF_SC_F + tid * 4 + 2] + sm[OFF_SC_F + tid * 4 + 3];
}

// =================== kernel 2: softmax over T per batch ===================
__global__ void __launch_bounds__(256) softmax_kernel(float* __restrict__ out) {
    __shared__ float red[256];
    int b = blockIdx.x, tid = threadIdx.x;
    float loc[8];
    float mx = -1e30f;
#pragma unroll
    for (int i = 0; i < 8; i++) {
        loc[i] = g_score[b * TN + tid + i * 256];
        mx = fmaxf(mx, loc[i]);
    }
    red[tid] = mx; __syncthreads();
    for (int s = 128; s; s >>= 1) { if (tid < s) red[tid] = fmaxf(red[tid], red[tid + s]); __syncthreads(); }
    float m = red[0]; __syncthreads();
    float sum = 0.f;
#pragma unroll
    for (int i = 0; i < 8; i++) { loc[i] = __expf(loc[i] - m); sum += loc[i]; }
    red[tid] = sum; __syncthreads();
    for (int s = 128; s; s >>= 1) { if (tid < s) red[tid] += red[tid + s]; __syncthreads(); }
    float inv = 1.f / red[0];
#pragma unroll
    for (int i = 0; i < 8; i++)
        out[BN * HN + b * TN + tid + i * 256] = loc[i] * inv;
}

// =================== kernel 3: context from fp16 values ===================
// grid (16, 32): 64-col chunk x batch; 256 thr = 64 cols x 4 T-slices.
__global__ void __launch_bounds__(256) context_kernel(float* __restrict__ out) {
    __shared__ float ws[TN];
    __shared__ float part[4][64];
    int b = blockIdx.y;
    int tid = threadIdx.x, tc = tid & 63, tq = tid >> 6;
    int col = blockIdx.x * 64 + tc;
    for (int i = tid; i < TN; i += 256) ws[i] = out[BN * HN + b * TN + i];
    __syncthreads();
    const __half* vp = g_vf16 + ((size_t)b * TN + tq * 512) * HN + col;
    float acc = 0.f;
#pragma unroll 16
    for (int t = 0; t < 512; t++)
        acc = fmaf(ws[tq * 512 + t], __half2float(vp[(size_t)t * HN]), acc);
    part[tq][tc] = acc;
    __syncthreads();
    if (tq == 0)
        out[b * HN + col] = part[0][tc] + part[1][tc] + part[2][tc] + part[3][tc];
}

// =================== launch ===================
extern "C" void kernel_launch(void* const* d_in, const int* in_sizes, int n_in,
                              void* d_out, int out_size) {
    const float* q      = (const float*)d_in[0];   // (1,32,1024)
    const float* values = (const float*)d_in[1];   // (32,2048,1024)
    const float* Ww     = (const float*)d_in[2];   // (1024,2048)
    const float* Wb     = (const float*)d_in[3];   // (1024,)
    const float* Vw     = (const float*)d_in[4];   // (1,1024)
    // d_in[5] = V_b : softmax-invariant, unused
    float* out = (float*)d_out;                    // [context 32*1024 | weights 32*2048]

    cvt_values_kernel<<<2960, 256>>>(values);
    cvt_wv_kernel<<<512, 256>>>(Ww);
    qbias_kernel<<<128, 256>>>(q, Ww, Wb);

    cudaFuncSetAttribute(gemm_score_kernel,
                         cudaFuncAttributeMaxDynamicSharedMemorySize, SMEM_BYTES);
    gemm_score_kernel<<<512, 512, SMEM_BYTES>>>(Vw);

    softmax_kernel<<<32, 256>>>(out);

    context_kernel<<<dim3(16, 32), 256>>>(out);
}

// round 8
// speedup vs baseline: 2.1987x; 1.0814x over previous
#include <cuda_runtime.h>
#include <cuda_fp16.h>
#include <cstdint>

// ---------------- problem constants ----------------
#define BN 32
#define TN 2048
#define HN 1024
#define UN 1024
#define SZ (BN * TN)

// ---------------- device scratch (no cudaMalloc allowed) ----------------
__device__ float  g_qbias[BN * UN];          // q@Wq^T + W_b (fp32, exact)
__device__ float  g_scp[4 * SZ];             // per-N-quarter partial scores
__device__ __half g_vf16[BN * TN * HN];      // values in fp16 (128MB)
__device__ __half g_wv16[UN * HN];           // Wv = W_w[:, :H] in fp16 (2MB)

// ---------------- helpers ----------------
__device__ __forceinline__ uint32_t smem_u32(const void* p) {
    uint32_t a;
    asm("{ .reg .u64 t; cvta.to.shared.u64 t, %1; cvt.u32.u64 %0, t; }" : "=r"(a) : "l"(p));
    return a;
}
__device__ __forceinline__ void mma16(float* d, const uint32_t* a, uint32_t b0, uint32_t b1) {
    asm volatile(
        "mma.sync.aligned.m16n8k16.row.col.f32.f16.f16.f32 "
        "{%0,%1,%2,%3}, {%4,%5,%6,%7}, {%8,%9}, {%0,%1,%2,%3};"
        : "+f"(d[0]), "+f"(d[1]), "+f"(d[2]), "+f"(d[3])
        : "r"(a[0]), "r"(a[1]), "r"(a[2]), "r"(a[3]), "r"(b0), "r"(b1));
}
__device__ __forceinline__ void ldsm4(uint32_t* r, uint32_t addr) {
    asm volatile("ldmatrix.sync.aligned.m8n8.x4.shared.b16 {%0,%1,%2,%3}, [%4];"
        : "=r"(r[0]), "=r"(r[1]), "=r"(r[2]), "=r"(r[3]) : "r"(addr));
}
#define CP16(dst, src) \
    asm volatile("cp.async.cg.shared.global [%0], [%1], 16;" :: "r"(dst), "l"(src))

// ---------------- gemm smem layout ----------------
// Stage (96KB): A = 2 sections x [128 rows x 128B], B (+32KB) = 2 sections x [256 x 128B].
// XOR swizzle within a row: 16B-chunk c stored at (c ^ (row&7)).
#define STG_BYTES 98304u
#define OFF_QB_F 49152   // = 2*STG_BYTES/4
#define OFF_VW_F 49408
#define OFF_SC_F 49664
#define SMEM_BYTES 200704

// =================== conversion kernels ===================
__global__ void __launch_bounds__(256) cvt_values_kernel(const float* __restrict__ src) {
    int i = blockIdx.x * 256 + threadIdx.x;
    const int stride = gridDim.x * 256;
    const int n8 = BN * TN * HN / 8;
    for (; i < n8; i += stride) {
        float4 f0 = ((const float4*)src)[2 * i];
        float4 f1 = ((const float4*)src)[2 * i + 1];
        __half2 h0 = __floats2half2_rn(f0.x, f0.y);
        __half2 h1 = __floats2half2_rn(f0.z, f0.w);
        __half2 h2 = __floats2half2_rn(f1.x, f1.y);
        __half2 h3 = __floats2half2_rn(f1.z, f1.w);
        uint4 u;
        u.x = *reinterpret_cast<unsigned*>(&h0);
        u.y = *reinterpret_cast<unsigned*>(&h1);
        u.z = *reinterpret_cast<unsigned*>(&h2);
        u.w = *reinterpret_cast<unsigned*>(&h3);
        reinterpret_cast<uint4*>(g_vf16)[i] = u;
    }
}
__global__ void __launch_bounds__(256) cvt_wv_kernel(const float* __restrict__ W) {
    // Wv = W_w[:, :HN]; row stride 2*HN
    int i = blockIdx.x * 256 + threadIdx.x;            // one per 8 elems; 131072 total
    int u = i >> 7, c8 = i & 127;
    const float4* s = (const float4*)(W + (size_t)u * (2 * HN) + c8 * 8);
    float4 f0 = s[0], f1 = s[1];
    __half2 h0 = __floats2half2_rn(f0.x, f0.y);
    __half2 h1 = __floats2half2_rn(f0.z, f0.w);
    __half2 h2 = __floats2half2_rn(f1.x, f1.y);
    __half2 h3 = __floats2half2_rn(f1.z, f1.w);
    uint4 v;
    v.x = *reinterpret_cast<unsigned*>(&h0);
    v.y = *reinterpret_cast<unsigned*>(&h1);
    v.z = *reinterpret_cast<unsigned*>(&h2);
    v.w = *reinterpret_cast<unsigned*>(&h3);
    reinterpret_cast<uint4*>(g_wv16)[i] = v;
}

// =================== kernel 0: qbias[b][u] = q[b] . Wq[u] + W_b[u] (fp32) ===================
__global__ void __launch_bounds__(256) qbias_kernel(const float* __restrict__ q,
                                                    const float* __restrict__ W,
                                                    const float* __restrict__ Wb) {
    int tid = threadIdx.x, lane = tid & 31, w = tid >> 5;
    int u = blockIdx.x * 8 + w;
    const float* wrow = W + (size_t)u * (2 * HN) + HN;   // Wq = W_w[:, H:]
    float wreg[32];
#pragma unroll
    for (int i = 0; i < 32; i++) wreg[i] = wrow[lane + i * 32];
    float wb = Wb[u];
    for (int b = 0; b < BN; b++) {
        const float* qb = q + b * HN;
        float acc = 0.f;
#pragma unroll
        for (int i = 0; i < 32; i++) acc = fmaf(wreg[i], qb[lane + i * 32], acc);
#pragma unroll
        for (int o = 16; o; o >>= 1) acc += __shfl_xor_sync(0xFFFFFFFFu, acc, o);
        if (lane == 0) g_qbias[b * UN + u] = acc + wb;
    }
}

// =================== kernel 1: fused fp16 GEMM + tanh reduce ===================
// Work unit = (m-tile, n-quarter): M=128 x N=256 x K=1024, 8 slabs of K=128.
// grid = 2048 (q-major: q = bid>>9 so each wave shares one L2-resident B quarter).
// 512 thr, 16 warps (4M x 4N), warp tile 32x64, 2-stage cp.async.
__global__ void __launch_bounds__(512, 1)
gemm_score_kernel(const float* __restrict__ Vw) {
    extern __shared__ float sm[];
    const uint32_t sbase = smem_u32(sm);
    const int tid = threadIdx.x;
    const int lane = tid & 31, wid = tid >> 5;
    const int wm = wid & 3, wn = wid >> 2;
    const int q  = blockIdx.x >> 9;                // n-quarter 0..3
    const int mt = blockIdx.x & 511;               // m-tile 0..511
    const size_t m0 = (size_t)mt * 128;
    const int b = mt >> 4;                         // 16 M-tiles per batch
    const int u0 = q * 256;

    sm[OFF_SC_F + tid] = 0.f;                      // 512 score partials (128 rows x 4 wn)
    if (tid < 256) {
        sm[OFF_QB_F + tid] = g_qbias[b * UN + u0 + tid];
        sm[OFF_VW_F + tid] = Vw[u0 + tid];
    }

    const int l7 = lane & 7;
    const int hiA = lane >> 4;                     // A k-chunk select
    const int hiB = (lane >> 3) & 1;               // B k-chunk select
    const uint32_t aRow = (uint32_t)(wm * 32 + (lane & 15)) * 128u;
    const uint32_t bRow = (uint32_t)(wn * 64 + ((lane >> 4) & 1) * 8 + l7) * 128u;

    auto load_slab = [&](int g) {
        const int k0 = g * 128;
        const uint32_t st = sbase + (uint32_t)(g & 1) * STG_BYTES;
#pragma unroll
        for (int i = 0; i < 4; i++) {              // A: 128 rows x 16 16B-chunks
            int idx = tid + i * 512;
            int row = idx >> 4, gc = idx & 15;
            uint32_t dst = st + (uint32_t)(gc >> 3) * 16384u + (uint32_t)row * 128u +
                           (uint32_t)(((gc & 7) ^ (row & 7)) << 4);
            CP16(dst, g_vf16 + (m0 + row) * HN + k0 + gc * 8);
        }
#pragma unroll
        for (int i = 0; i < 8; i++) {              // B: 256 rows x 16 16B-chunks
            int idx = tid + i * 512;
            int row = idx >> 4, gc = idx & 15;
            uint32_t dst = st + 32768u + (uint32_t)(gc >> 3) * 32768u +
                           (uint32_t)row * 128u +
                           (uint32_t)(((gc & 7) ^ (row & 7)) << 4);
            CP16(dst, g_wv16 + (size_t)(u0 + row) * HN + k0 + gc * 8);
        }
        asm volatile("cp.async.commit_group;" ::: "memory");
    };

    float acc[2][8][4];
#pragma unroll
    for (int i = 0; i < 2; i++)
#pragma unroll
        for (int j = 0; j < 8; j++)
#pragma unroll
            for (int k = 0; k < 4; k++) acc[i][j][k] = 0.f;

    load_slab(0);

    for (int g = 0; g < 8; g++) {
        asm volatile("cp.async.wait_group 0;" ::: "memory");
        __syncthreads();
        if (g + 1 < 8) load_slab(g + 1);

        const uint32_t st = sbase + (uint32_t)(g & 1) * STG_BYTES;
        const uint32_t aB = st + aRow;
        const uint32_t bB = st + 32768u + bRow;
#pragma unroll
        for (int kk = 0; kk < 8; kk++) {           // 8 x k16
            const uint32_t sA = (uint32_t)(kk >> 2) * 16384u;
            const uint32_t sB = (uint32_t)(kk >> 2) * 32768u;
            const int c0 = (kk & 3) * 2;
            const uint32_t swA = (uint32_t)(((c0 + hiA) ^ l7) << 4);
            const uint32_t swB = (uint32_t)(((c0 + hiB) ^ l7) << 4);
            uint32_t af[2][4], bf[4][4];
#pragma unroll
            for (int ms = 0; ms < 2; ms++)
                ldsm4(af[ms], aB + sA + (uint32_t)ms * 2048u + swA);
#pragma unroll
            for (int j = 0; j < 4; j++)
                ldsm4(bf[j], bB + sB + (uint32_t)j * 2048u + swB);
#pragma unroll
            for (int ms = 0; ms < 2; ms++)
#pragma unroll
                for (int j = 0; j < 4; j++) {
                    mma16(acc[ms][2 * j],     af[ms], bf[j][0], bf[j][1]);
                    mma16(acc[ms][2 * j + 1], af[ms], bf[j][2], bf[j][3]);
                }
        }
    }

    // ---- epilogue: rsum[row] = sum_col tanh(acc + qbias) * Vw over this quarter ----
    float rsum[2][2];
#pragma unroll
    for (int ms = 0; ms < 2; ms++) { rsum[ms][0] = 0.f; rsum[ms][1] = 0.f; }
#pragma unroll
    for (int ms = 0; ms < 2; ms++)
#pragma unroll
        for (int ns = 0; ns < 8; ns++)
#pragma unroll
            for (int d = 0; d < 4; d++) {
                int col = wn * 64 + ns * 8 + (lane & 3) * 2 + (d & 1);
                float x = acc[ms][ns][d] + sm[OFF_QB_F + col];
                float e = __expf(x + x);
                float th = 1.f - 2.f / (e + 1.f);   // exact tanh, stable both tails
                rsum[ms][d >> 1] = fmaf(th, sm[OFF_VW_F + col], rsum[ms][d >> 1]);
            }
#pragma unroll
    for (int ms = 0; ms < 2; ms++)
#pragma unroll
        for (int hi = 0; hi < 2; hi++) {
            float v = rsum[ms][hi];
            v += __shfl_xor_sync(0xFFFFFFFFu, v, 1);
            v += __shfl_xor_sync(0xFFFFFFFFu, v, 2);
            if ((lane & 3) == 0) {
                int row = wm * 32 + ms * 16 + hi * 8 + (lane >> 2);
                sm[OFF_SC_F + row * 4 + wn] += v;   // unique (row, wn) writer
            }
        }
    __syncthreads();

    if (tid < 128)
        g_scp[q * SZ + m0 + tid] =
            sm[OFF_SC_F + tid * 4]     + sm[OFF_SC_F + tid * 4 + 1] +
            sm[OFF_SC_F + tid * 4 + 2] + sm[OFF_SC_F + tid * 4 + 3];
}

// =================== kernel 2: softmax over T per batch (sums 4 quarter partials) ===================
__global__ void __launch_bounds__(256) softmax_kernel(float* __restrict__ out) {
    __shared__ float red[256];
    int b = blockIdx.x, tid = threadIdx.x;
    float loc[8];
    float mx = -1e30f;
#pragma unroll
    for (int i = 0; i < 8; i++) {
        int idx = b * TN + tid + i * 256;
        loc[i] = (g_scp[idx] + g_scp[SZ + idx]) +
                 (g_scp[2 * SZ + idx] + g_scp[3 * SZ + idx]);
        mx = fmaxf(mx, loc[i]);
    }
    red[tid] = mx; __syncthreads();
    for (int s = 128; s; s >>= 1) { if (tid < s) red[tid] = fmaxf(red[tid], red[tid + s]); __syncthreads(); }
    float m = red[0]; __syncthreads();
    float sum = 0.f;
#pragma unroll
    for (int i = 0; i < 8; i++) { loc[i] = __expf(loc[i] - m); sum += loc[i]; }
    red[tid] = sum; __syncthreads();
    for (int s = 128; s; s >>= 1) { if (tid < s) red[tid] += red[tid + s]; __syncthreads(); }
    float inv = 1.f / red[0];
#pragma unroll
    for (int i = 0; i < 8; i++)
        out[BN * HN + b * TN + tid + i * 256] = loc[i] * inv;
}

// =================== kernel 3: context from fp16 values ===================
// grid (16, 32): 64-col chunk x batch; 256 thr = 64 cols x 4 T-slices.
__global__ void __launch_bounds__(256) context_kernel(float* __restrict__ out) {
    __shared__ float ws[TN];
    __shared__ float part[4][64];
    int b = blockIdx.y;
    int tid = threadIdx.x, tc = tid & 63, tq = tid >> 6;
    int col = blockIdx.x * 64 + tc;
    for (int i = tid; i < TN; i += 256) ws[i] = out[BN * HN + b * TN + i];
    __syncthreads();
    const __half* vp = g_vf16 + ((size_t)b * TN + tq * 512) * HN + col;
    float acc = 0.f;
#pragma unroll 16
    for (int t = 0; t < 512; t++)
        acc = fmaf(ws[tq * 512 + t], __half2float(vp[(size_t)t * HN]), acc);
    part[tq][tc] = acc;
    __syncthreads();
    if (tq == 0)
        out[b * HN + col] = part[0][tc] + part[1][tc] + part[2][tc] + part[3][tc];
}

// =================== launch ===================
extern "C" void kernel_launch(void* const* d_in, const int* in_sizes, int n_in,
                              void* d_out, int out_size) {
    const float* q      = (const float*)d_in[0];   // (1,32,1024)
    const float* values = (const float*)d_in[1];   // (32,2048,1024)
    const float* Ww     = (const float*)d_in[2];   // (1024,2048)
    const float* Wb     = (const float*)d_in[3];   // (1024,)
    const float* Vw     = (const float*)d_in[4];   // (1,1024)
    // d_in[5] = V_b : softmax-invariant, unused
    float* out = (float*)d_out;                    // [context 32*1024 | weights 32*2048]

    cvt_values_kernel<<<2960, 256>>>(values);
    cvt_wv_kernel<<<512, 256>>>(Ww);
    qbias_kernel<<<128, 256>>>(q, Ww, Wb);

    cudaFuncSetAttribute(gemm_score_kernel,
                         cudaFuncAttributeMaxDynamicSharedMemorySize, SMEM_BYTES);
    gemm_score_kernel<<<2048, 512, SMEM_BYTES>>>(Vw);

    softmax_kernel<<<32, 256>>>(out);

    context_kernel<<<dim3(16, 32), 256>>>(out);
}